// round 12
// baseline (speedup 1.0000x reference)
#include <cuda_runtime.h>
#include <cuda_bf16.h>
#include <cstdint>

#define THREADS 512
#define TBR     64
#define IN_DIM  65
#define H1      128
#define H2      64
#define OUTD    256

// ---------------- smem byte offsets ----------------
#define OFF_W1H  0        // [128][64] bf16 swz, 16384
#define OFF_W1L  16384
#define OFF_W2H  32768    // [64][128] bf16 swz, 16384
#define OFF_W2L  49152
#define OFF_W3H  65536    // [256][64] bf16 swz, 32768
#define OFF_W3L  98304
#define OFF_AH   131072   // [64][64]  bf16 swz, 8192
#define OFF_AL   139264
#define OFF_X1H  147456   // [64][128] bf16 swz, 16384
#define OFF_X1L  163840
#define OFF_X2H  180224   // [64][64]  bf16 swz, 8192
#define OFF_X2L  188416
#define OFF_B1   196608   // 512
#define OFF_B2   197120   // 256
#define OFF_B3   197376   // 1024
#define OFF_C64  198400   // 512 (W1 column 64, fp32)
#define OFF_DIM  198912   // 256
#define OFF_SC   199168   // 256 (int)
#define OFF_PMAX 199424   // 8*64*4 = 2048
#define OFF_PSUM 201472   // 2048
#define SMEM_BYTES 203520

__device__ __forceinline__ uint32_t smem_u32(const void* p) {
    uint32_t a;
    asm("{ .reg .u64 t; cvta.to.shared.u64 t, %1; cvt.u32.u64 %0, t; }" : "=r"(a) : "l"(p));
    return a;
}
// swizzled byte offset of bf16 element (r,k), row stride sB bytes
__device__ __forceinline__ uint32_t swoff(int r, int k, int sB) {
    return (uint32_t)(r * sB) + (uint32_t)((((k >> 3) ^ (r & 7)) << 4) + ((k & 7) << 1));
}
__device__ __forceinline__ float bf16rt(float x) {
    return __bfloat162float(__float2bfloat16_rn(x));
}
__device__ __forceinline__ uint32_t pack2(float a, float b) {
    uint32_t lo = (uint32_t)__bfloat16_as_ushort(__float2bfloat16_rn(a));
    uint32_t hi = (uint32_t)__bfloat16_as_ushort(__float2bfloat16_rn(b));
    return lo | (hi << 16);
}
__device__ __forceinline__ void ldsm4(uint32_t (&a)[4], uint32_t addr) {
    asm volatile("ldmatrix.sync.aligned.m8n8.x4.shared.b16 {%0,%1,%2,%3}, [%4];"
        : "=r"(a[0]), "=r"(a[1]), "=r"(a[2]), "=r"(a[3]) : "r"(addr));
}
__device__ __forceinline__ void mmabf(float (&d)[4], const uint32_t (&a)[4],
                                      uint32_t b0, uint32_t b1) {
    asm volatile("mma.sync.aligned.m16n8k16.row.col.f32.bf16.bf16.f32 "
        "{%0,%1,%2,%3},{%4,%5,%6,%7},{%8,%9},{%0,%1,%2,%3};"
        : "+f"(d[0]), "+f"(d[1]), "+f"(d[2]), "+f"(d[3])
        : "r"(a[0]), "r"(a[1]), "r"(a[2]), "r"(a[3]), "r"(b0), "r"(b1));
}

__global__ void __launch_bounds__(THREADS, 1)
policy_mma_kernel(const float* __restrict__ gIn, const int* __restrict__ gScaleTab,
                  const float* __restrict__ gW1, const float* __restrict__ gB1,
                  const float* __restrict__ gW2, const float* __restrict__ gB2,
                  const float* __restrict__ gW3, const float* __restrict__ gB3,
                  float* __restrict__ gProbs, float* __restrict__ gMask,
                  int Bsz, int numTiles)
{
    extern __shared__ char smc[];
    const int tid  = threadIdx.x;
    const int lane = tid & 31;
    const int wid  = tid >> 5;
    const int wM   = wid >> 3;     // 0..1 (32 rows each)
    const int wN   = wid & 7;      // 0..7
    const uint32_t sb = smem_u32(smc);

    float* sB1  = (float*)(smc + OFF_B1);
    float* sB2  = (float*)(smc + OFF_B2);
    float* sB3  = (float*)(smc + OFF_B3);
    float* sC64 = (float*)(smc + OFF_C64);
    float* sDim = (float*)(smc + OFF_DIM);
    int*   sSc  = (int*)  (smc + OFF_SC);
    float* sPMax = (float*)(smc + OFF_PMAX);
    float* sPSum = (float*)(smc + OFF_PSUM);

    // ---- one-time: stage weights as bf16 hi/lo into swizzled layouts ----
    for (int idx = tid; idx < H1 * 64; idx += THREADS) {          // W1[:, 0:64]
        int n = idx >> 6, k = idx & 63;
        float x = gW1[n * IN_DIM + k];
        float h = bf16rt(x);
        uint32_t o = swoff(n, k, 128);
        *(__nv_bfloat16*)(smc + OFF_W1H + o) = __float2bfloat16_rn(h);
        *(__nv_bfloat16*)(smc + OFF_W1L + o) = __float2bfloat16_rn(x - h);
    }
    for (int n = tid; n < H1; n += THREADS) sC64[n] = gW1[n * IN_DIM + 64];
    for (int idx = tid; idx < H2 * H1; idx += THREADS) {          // W2 [64][128]
        int n = idx >> 7, k = idx & 127;
        float x = gW2[idx];
        float h = bf16rt(x);
        uint32_t o = swoff(n, k, 256);
        *(__nv_bfloat16*)(smc + OFF_W2H + o) = __float2bfloat16_rn(h);
        *(__nv_bfloat16*)(smc + OFF_W2L + o) = __float2bfloat16_rn(x - h);
    }
    for (int idx = tid; idx < OUTD * H2; idx += THREADS) {        // W3 [256][64]
        int n = idx >> 6, k = idx & 63;
        float x = gW3[idx];
        float h = bf16rt(x);
        uint32_t o = swoff(n, k, 128);
        *(__nv_bfloat16*)(smc + OFF_W3H + o) = __float2bfloat16_rn(h);
        *(__nv_bfloat16*)(smc + OFF_W3L + o) = __float2bfloat16_rn(x - h);
    }
    for (int i = tid; i < H1; i += THREADS)   sB1[i] = gB1[i];
    for (int i = tid; i < H2; i += THREADS)   sB2[i] = gB2[i];
    for (int i = tid; i < OUTD; i += THREADS) sB3[i] = gB3[i];
    __syncthreads();

    for (int tile = blockIdx.x; tile < numTiles; tile += gridDim.x) {

        // ---------- phase 0: load input tile (cols 0..63 -> A hi/lo) ----------
        {
            int row = tid >> 3, q = tid & 7;       // 8 threads per row, 8 cols each
            long long grow = (long long)tile * TBR + row;
            if (grow < (long long)Bsz) {
                const float* ip = gIn + (size_t)grow * IN_DIM;
                #pragma unroll
                for (int j = 0; j < 4; ++j) {
                    float a = ip[q * 8 + 2 * j], b = ip[q * 8 + 2 * j + 1];
                    float ah = bf16rt(a), bh = bf16rt(b);
                    uint32_t o = swoff(row, q * 8 + 2 * j, 128);
                    *(uint32_t*)(smc + OFF_AH + o) = pack2(ah, bh);
                    *(uint32_t*)(smc + OFF_AL + o) = pack2(a - ah, b - bh);
                }
                if (q == 0) {
                    float dv = ip[64];
                    sDim[row] = dv;
                    int di = (int)dv; di = di < 0 ? 0 : (di > 15 ? 15 : di);
                    sSc[row] = gScaleTab[di];
                }
            } else {
                #pragma unroll
                for (int j = 0; j < 4; ++j) {
                    uint32_t o = swoff(row, q * 8 + 2 * j, 128);
                    *(uint32_t*)(smc + OFF_AH + o) = 0;
                    *(uint32_t*)(smc + OFF_AL + o) = 0;
                }
                if (q == 0) { sDim[row] = 0.f; sSc[row] = OUTD; }
            }
        }
        __syncthreads();

        // ---------- GEMM1: [64x128] = A[64x64] @ W1^T (warp: 32r x 16c) ----------
        float acc1[2][2][4];
        #pragma unroll
        for (int mi = 0; mi < 2; ++mi)
            #pragma unroll
            for (int ni = 0; ni < 2; ++ni)
                #pragma unroll
                for (int d = 0; d < 4; ++d) acc1[mi][ni][d] = 0.f;
        #pragma unroll
        for (int ks = 0; ks < 4; ++ks) {
            uint32_t Ah[2][4], Al[2][4], Bh[4], Bl[4];
            #pragma unroll
            for (int mi = 0; mi < 2; ++mi) {
                int r = wM * 32 + mi * 16 + (lane & 15);
                uint32_t kch = (uint32_t)(ks * 2 + (lane >> 4));
                uint32_t o = (uint32_t)(r * 128) + ((kch ^ (uint32_t)(r & 7)) << 4);
                ldsm4(Ah[mi], sb + OFF_AH + o);
                ldsm4(Al[mi], sb + OFF_AL + o);
            }
            {
                int n = wN * 16 + ((lane >> 4) << 3) + (lane & 7);
                uint32_t kch = (uint32_t)(ks * 2 + ((lane >> 3) & 1));
                uint32_t o = (uint32_t)(n * 128) + ((kch ^ (uint32_t)(n & 7)) << 4);
                ldsm4(Bh, sb + OFF_W1H + o);
                ldsm4(Bl, sb + OFF_W1L + o);
            }
            #pragma unroll
            for (int mi = 0; mi < 2; ++mi)
                #pragma unroll
                for (int h = 0; h < 2; ++h) {
                    mmabf(acc1[mi][h], Ah[mi], Bh[h*2], Bh[h*2+1]);
                    mmabf(acc1[mi][h], Ah[mi], Bl[h*2], Bl[h*2+1]);
                    mmabf(acc1[mi][h], Al[mi], Bh[h*2], Bh[h*2+1]);
                }
        }
        // epilogue 1: bias + exact dim-column correction + relu -> X1 hi/lo
        #pragma unroll
        for (int mi = 0; mi < 2; ++mi) {
            int r0 = wM * 32 + mi * 16 + (lane >> 2), r1 = r0 + 8;
            float d0 = sDim[r0], d1 = sDim[r1];
            #pragma unroll
            for (int ni = 0; ni < 2; ++ni) {
                int c0 = wN * 16 + ni * 8 + ((lane & 3) << 1);
                float bb0 = sB1[c0], bb1 = sB1[c0+1];
                float w0 = sC64[c0], w1 = sC64[c0+1];
                float v00 = fmaxf(acc1[mi][ni][0] + bb0 + d0 * w0, 0.f);
                float v01 = fmaxf(acc1[mi][ni][1] + bb1 + d0 * w1, 0.f);
                float v10 = fmaxf(acc1[mi][ni][2] + bb0 + d1 * w0, 0.f);
                float v11 = fmaxf(acc1[mi][ni][3] + bb1 + d1 * w1, 0.f);
                float h00 = bf16rt(v00), h01 = bf16rt(v01);
                float h10 = bf16rt(v10), h11 = bf16rt(v11);
                uint32_t o0 = swoff(r0, c0, 256), o1 = swoff(r1, c0, 256);
                *(uint32_t*)(smc + OFF_X1H + o0) = pack2(h00, h01);
                *(uint32_t*)(smc + OFF_X1L + o0) = pack2(v00 - h00, v01 - h01);
                *(uint32_t*)(smc + OFF_X1H + o1) = pack2(h10, h11);
                *(uint32_t*)(smc + OFF_X1L + o1) = pack2(v10 - h10, v11 - h11);
            }
        }
        __syncthreads();

        // ---------- GEMM2: [64x64] = X1[64x128] @ W2^T (warp: 32r x 8c) ----------
        float acc2[2][4];
        #pragma unroll
        for (int mi = 0; mi < 2; ++mi)
            #pragma unroll
            for (int d = 0; d < 4; ++d) acc2[mi][d] = 0.f;
        #pragma unroll
        for (int ks2 = 0; ks2 < 4; ++ks2) {
            // B: one ldsm4 covers TWO ks steps (4 k-chunks of the same n8)
            uint32_t Bh[4], Bl[4];
            {
                int n = wN * 8 + (lane & 7);
                uint32_t kch = (uint32_t)(ks2 * 4 + (lane >> 3));
                uint32_t o = (uint32_t)(n * 256) + ((kch ^ (uint32_t)(n & 7)) << 4);
                ldsm4(Bh, sb + OFF_W2H + o);
                ldsm4(Bl, sb + OFF_W2L + o);
            }
            #pragma unroll
            for (int s = 0; s < 2; ++s) {
                int ks = ks2 * 2 + s;
                uint32_t Ah[2][4], Al[2][4];
                #pragma unroll
                for (int mi = 0; mi < 2; ++mi) {
                    int r = wM * 32 + mi * 16 + (lane & 15);
                    uint32_t kch = (uint32_t)(ks * 2 + (lane >> 4));
                    uint32_t o = (uint32_t)(r * 256) + ((kch ^ (uint32_t)(r & 7)) << 4);
                    ldsm4(Ah[mi], sb + OFF_X1H + o);
                    ldsm4(Al[mi], sb + OFF_X1L + o);
                }
                #pragma unroll
                for (int mi = 0; mi < 2; ++mi) {
                    mmabf(acc2[mi], Ah[mi], Bh[s*2], Bh[s*2+1]);
                    mmabf(acc2[mi], Ah[mi], Bl[s*2], Bl[s*2+1]);
                    mmabf(acc2[mi], Al[mi], Bh[s*2], Bh[s*2+1]);
                }
            }
        }
        // epilogue 2 -> X2 hi/lo
        #pragma unroll
        for (int mi = 0; mi < 2; ++mi) {
            int r0 = wM * 32 + mi * 16 + (lane >> 2), r1 = r0 + 8;
            int c0 = wN * 8 + ((lane & 3) << 1);
            float bb0 = sB2[c0], bb1 = sB2[c0+1];
            float v00 = fmaxf(acc2[mi][0] + bb0, 0.f);
            float v01 = fmaxf(acc2[mi][1] + bb1, 0.f);
            float v10 = fmaxf(acc2[mi][2] + bb0, 0.f);
            float v11 = fmaxf(acc2[mi][3] + bb1, 0.f);
            float h00 = bf16rt(v00), h01 = bf16rt(v01);
            float h10 = bf16rt(v10), h11 = bf16rt(v11);
            uint32_t o0 = swoff(r0, c0, 128), o1 = swoff(r1, c0, 128);
            *(uint32_t*)(smc + OFF_X2H + o0) = pack2(h00, h01);
            *(uint32_t*)(smc + OFF_X2L + o0) = pack2(v00 - h00, v01 - h01);
            *(uint32_t*)(smc + OFF_X2H + o1) = pack2(h10, h11);
            *(uint32_t*)(smc + OFF_X2L + o1) = pack2(v10 - h10, v11 - h11);
        }
        __syncthreads();

        // ---------- GEMM3: [64x256] = X2[64x64] @ W3^T (warp: 32r x 32c) ----------
        float acc3[2][4][4];
        #pragma unroll
        for (int mi = 0; mi < 2; ++mi)
            #pragma unroll
            for (int ni = 0; ni < 4; ++ni)
                #pragma unroll
                for (int d = 0; d < 4; ++d) acc3[mi][ni][d] = 0.f;
        #pragma unroll
        for (int ks = 0; ks < 4; ++ks) {
            uint32_t Ah[2][4], Al[2][4];
            #pragma unroll
            for (int mi = 0; mi < 2; ++mi) {
                int r = wM * 32 + mi * 16 + (lane & 15);
                uint32_t kch = (uint32_t)(ks * 2 + (lane >> 4));
                uint32_t o = (uint32_t)(r * 128) + ((kch ^ (uint32_t)(r & 7)) << 4);
                ldsm4(Ah[mi], sb + OFF_X2H + o);
                ldsm4(Al[mi], sb + OFF_X2L + o);
            }
            #pragma unroll
            for (int np = 0; np < 2; ++np) {
                uint32_t Bh[4], Bl[4];
                int n = wN * 32 + np * 16 + ((lane >> 4) << 3) + (lane & 7);
                uint32_t kch = (uint32_t)(ks * 2 + ((lane >> 3) & 1));
                uint32_t o = (uint32_t)(n * 128) + ((kch ^ (uint32_t)(n & 7)) << 4);
                ldsm4(Bh, sb + OFF_W3H + o);
                ldsm4(Bl, sb + OFF_W3L + o);
                #pragma unroll
                for (int mi = 0; mi < 2; ++mi)
                    #pragma unroll
                    for (int h = 0; h < 2; ++h) {
                        int ni = np * 2 + h;
                        mmabf(acc3[mi][ni], Ah[mi], Bh[h*2], Bh[h*2+1]);
                        mmabf(acc3[mi][ni], Ah[mi], Bl[h*2], Bl[h*2+1]);
                        mmabf(acc3[mi][ni], Al[mi], Bh[h*2], Bh[h*2+1]);
                    }
            }
        }

        // ---------- epilogue 3: bias + masked softmax + stores ----------
        {
            #pragma unroll
            for (int mi = 0; mi < 2; ++mi)
                #pragma unroll
                for (int h = 0; h < 2; ++h) {
                    int r = wM * 32 + mi * 16 + (lane >> 2) + h * 8;
                    int scale = sSc[r];
                    float m = -3.4e38f;
                    #pragma unroll
                    for (int ni = 0; ni < 4; ++ni) {
                        int c0 = wN * 32 + ni * 8 + ((lane & 3) << 1);
                        float v0 = acc3[mi][ni][h*2]   + sB3[c0];
                        float v1 = acc3[mi][ni][h*2+1] + sB3[c0+1];
                        acc3[mi][ni][h*2]   = v0;
                        acc3[mi][ni][h*2+1] = v1;
                        if (c0     < scale) m = fmaxf(m, v0);
                        if (c0 + 1 < scale) m = fmaxf(m, v1);
                    }
                    m = fmaxf(m, __shfl_xor_sync(0xffffffffu, m, 1));
                    m = fmaxf(m, __shfl_xor_sync(0xffffffffu, m, 2));
                    if ((lane & 3) == 0) sPMax[wN * 64 + r] = m;
                }
            __syncthreads();
            #pragma unroll
            for (int mi = 0; mi < 2; ++mi)
                #pragma unroll
                for (int h = 0; h < 2; ++h) {
                    int r = wM * 32 + mi * 16 + (lane >> 2) + h * 8;
                    int scale = sSc[r];
                    float gm = -3.4e38f;
                    #pragma unroll
                    for (int w = 0; w < 8; ++w)
                        gm = fmaxf(gm, sPMax[w * 64 + r]);
                    float s = 0.f;
                    #pragma unroll
                    for (int ni = 0; ni < 4; ++ni) {
                        int c0 = wN * 32 + ni * 8 + ((lane & 3) << 1);
                        float e0 = (c0     < scale) ? __expf(acc3[mi][ni][h*2]   - gm) : 0.f;
                        float e1 = (c0 + 1 < scale) ? __expf(acc3[mi][ni][h*2+1] - gm) : 0.f;
                        acc3[mi][ni][h*2]   = e0;
                        acc3[mi][ni][h*2+1] = e1;
                        s += e0 + e1;
                    }
                    s += __shfl_xor_sync(0xffffffffu, s, 1);
                    s += __shfl_xor_sync(0xffffffffu, s, 2);
                    if ((lane & 3) == 0) sPSum[wN * 64 + r] = s;
                }
            __syncthreads();
            long long rowG0 = (long long)tile * TBR;
            #pragma unroll
            for (int mi = 0; mi < 2; ++mi)
                #pragma unroll
                for (int h = 0; h < 2; ++h) {
                    int r = wM * 32 + mi * 16 + (lane >> 2) + h * 8;
                    long long grow = rowG0 + r;
                    float ssum = 0.f;
                    #pragma unroll
                    for (int w = 0; w < 8; ++w)
                        ssum += sPSum[w * 64 + r];
                    float inv = 1.f / ssum;
                    if (grow < (long long)Bsz) {
                        float* po = gProbs + (size_t)grow * OUTD;
                        #pragma unroll
                        for (int ni = 0; ni < 4; ++ni) {
                            int c0 = wN * 32 + ni * 8 + ((lane & 3) << 1);
                            float2 t;
                            t.x = acc3[mi][ni][h*2]   * inv;
                            t.y = acc3[mi][ni][h*2+1] * inv;
                            *(float2*)(po + c0) = t;
                        }
                    }
                }
            // mask output (coalesced)
            if (gMask) {
                #pragma unroll
                for (int i = 0; i < 8; ++i) {
                    int g = tid + THREADS * i;
                    int row = g >> 6, c4 = g & 63;
                    long long grow = rowG0 + row;
                    if (grow < (long long)Bsz) {
                        int sc = sSc[row];
                        int c0 = c4 * 4;
                        float4 t;
                        t.x = (c0     < sc) ? 1.f : 0.f;
                        t.y = (c0 + 1 < sc) ? 1.f : 0.f;
                        t.z = (c0 + 2 < sc) ? 1.f : 0.f;
                        t.w = (c0 + 3 < sc) ? 1.f : 0.f;
                        *(float4*)(gMask + (size_t)grow * OUTD + c0) = t;
                    }
                }
            }
        }
        __syncthreads();   // protect sSc/sDim/A/X buffers before next tile
    }
}

extern "C" void kernel_launch(void* const* d_in, const int* in_sizes, int n_in,
                              void* d_out, int out_size)
{
    const float* gIn    = (const float*)d_in[0];
    const int*   gScale = (const int*)  d_in[1];
    const float* gW1    = (const float*)d_in[2];
    const float* gB1    = (const float*)d_in[3];
    const float* gW2    = (const float*)d_in[4];
    const float* gB2    = (const float*)d_in[5];
    const float* gW3    = (const float*)d_in[6];
    const float* gB3    = (const float*)d_in[7];

    int Bsz = in_sizes[0] / IN_DIM;
    int numTiles = (Bsz + TBR - 1) / TBR;

    float* gProbs = (float*)d_out;
    float* gMask  = nullptr;
    long long need2 = 2LL * Bsz * OUTD;
    if ((long long)out_size >= need2)
        gMask = gProbs + (size_t)Bsz * OUTD;

    cudaFuncSetAttribute(policy_mma_kernel,
                         cudaFuncAttributeMaxDynamicSharedMemorySize, SMEM_BYTES);

    int smCount = 148;
    cudaDeviceGetAttribute(&smCount, cudaDevAttrMultiProcessorCount, 0);
    int grid = numTiles < smCount ? numTiles : smCount;

    policy_mma_kernel<<<grid, THREADS, SMEM_BYTES>>>(
        gIn, gScale, gW1, gB1, gW2, gB2, gW3, gB3,
        gProbs, gMask, Bsz, numTiles);
}

// round 13
// speedup vs baseline: 1.2191x; 1.2191x over previous
#include <cuda_runtime.h>
#include <cuda_fp16.h>
#include <cstdint>

#define THREADS 512
#define TBR     64
#define IN_DIM  65
#define H1      128
#define H2      64
#define OUTD    256

// ---------------- smem byte offsets ----------------
#define OFF_W1H  0        // [128][64] fp16 swz, 16384
#define OFF_W1L  16384
#define OFF_W2H  32768    // [64][128] fp16 swz, 16384
#define OFF_W2L  49152
#define OFF_W3H  65536    // [256][64] fp16 swz, 32768
#define OFF_W3L  98304
#define OFF_AH   131072   // [64][64]  fp16 swz, 8192
#define OFF_X1H  139264   // [64][128] fp16 swz, 16384
#define OFF_X2H  155648   // [64][64]  fp16 swz, 8192
#define OFF_B1   163840   // 512
#define OFF_B2   164352   // 256
#define OFF_B3   164608   // 1024
#define OFF_C64  165632   // 512 (W1 column 64, fp32)
#define OFF_DIM  166144   // 256
#define OFF_SC   166400   // 256 (int)
#define OFF_PMAX 166656   // 8*64*4 = 2048
#define OFF_PSUM 168704   // 2048
#define SMEM_BYTES 170752

__device__ __forceinline__ uint32_t smem_u32(const void* p) {
    uint32_t a;
    asm("{ .reg .u64 t; cvta.to.shared.u64 t, %1; cvt.u32.u64 %0, t; }" : "=r"(a) : "l"(p));
    return a;
}
// swizzled byte offset of fp16 element (r,k), row stride sB bytes
__device__ __forceinline__ uint32_t swoff(int r, int k, int sB) {
    return (uint32_t)(r * sB) + (uint32_t)((((k >> 3) ^ (r & 7)) << 4) + ((k & 7) << 1));
}
__device__ __forceinline__ float h16rt(float x) {
    return __half2float(__float2half_rn(x));
}
__device__ __forceinline__ uint32_t pack2h(float a, float b) {
    __half2 t = __floats2half2_rn(a, b);
    return *(uint32_t*)&t;
}
__device__ __forceinline__ void ldsm4(uint32_t (&a)[4], uint32_t addr) {
    asm volatile("ldmatrix.sync.aligned.m8n8.x4.shared.b16 {%0,%1,%2,%3}, [%4];"
        : "=r"(a[0]), "=r"(a[1]), "=r"(a[2]), "=r"(a[3]) : "r"(addr));
}
__device__ __forceinline__ void mmah(float (&d)[4], const uint32_t (&a)[4],
                                     uint32_t b0, uint32_t b1) {
    asm volatile("mma.sync.aligned.m16n8k16.row.col.f32.f16.f16.f32 "
        "{%0,%1,%2,%3},{%4,%5,%6,%7},{%8,%9},{%0,%1,%2,%3};"
        : "+f"(d[0]), "+f"(d[1]), "+f"(d[2]), "+f"(d[3])
        : "r"(a[0]), "r"(a[1]), "r"(a[2]), "r"(a[3]), "r"(b0), "r"(b1));
}

__global__ void __launch_bounds__(THREADS, 1)
policy_mma_kernel(const float* __restrict__ gIn, const int* __restrict__ gScaleTab,
                  const float* __restrict__ gW1, const float* __restrict__ gB1,
                  const float* __restrict__ gW2, const float* __restrict__ gB2,
                  const float* __restrict__ gW3, const float* __restrict__ gB3,
                  float* __restrict__ gProbs, float* __restrict__ gMask,
                  int Bsz, int numTiles)
{
    extern __shared__ char smc[];
    const int tid  = threadIdx.x;
    const int lane = tid & 31;
    const int wid  = tid >> 5;
    const int wM   = wid >> 3;     // 0..1 (32 rows each)
    const int wN   = wid & 7;      // 0..7
    const uint32_t sb = smem_u32(smc);

    float* sB1  = (float*)(smc + OFF_B1);
    float* sB2  = (float*)(smc + OFF_B2);
    float* sB3  = (float*)(smc + OFF_B3);
    float* sC64 = (float*)(smc + OFF_C64);
    float* sDim = (float*)(smc + OFF_DIM);
    int*   sSc  = (int*)  (smc + OFF_SC);
    float* sPMax = (float*)(smc + OFF_PMAX);
    float* sPSum = (float*)(smc + OFF_PSUM);

    // ---- one-time: stage weights as fp16 hi/lo into swizzled layouts ----
    for (int idx = tid; idx < H1 * 64; idx += THREADS) {          // W1[:, 0:64]
        int n = idx >> 6, k = idx & 63;
        float x = gW1[n * IN_DIM + k];
        float h = h16rt(x);
        uint32_t o = swoff(n, k, 128);
        *(__half*)(smc + OFF_W1H + o) = __float2half_rn(h);
        *(__half*)(smc + OFF_W1L + o) = __float2half_rn(x - h);
    }
    for (int n = tid; n < H1; n += THREADS) sC64[n] = gW1[n * IN_DIM + 64];
    for (int idx = tid; idx < H2 * H1; idx += THREADS) {          // W2 [64][128]
        int n = idx >> 7, k = idx & 127;
        float x = gW2[idx];
        float h = h16rt(x);
        uint32_t o = swoff(n, k, 256);
        *(__half*)(smc + OFF_W2H + o) = __float2half_rn(h);
        *(__half*)(smc + OFF_W2L + o) = __float2half_rn(x - h);
    }
    for (int idx = tid; idx < OUTD * H2; idx += THREADS) {        // W3 [256][64]
        int n = idx >> 6, k = idx & 63;
        float x = gW3[idx];
        float h = h16rt(x);
        uint32_t o = swoff(n, k, 128);
        *(__half*)(smc + OFF_W3H + o) = __float2half_rn(h);
        *(__half*)(smc + OFF_W3L + o) = __float2half_rn(x - h);
    }
    for (int i = tid; i < H1; i += THREADS)   sB1[i] = gB1[i];
    for (int i = tid; i < H2; i += THREADS)   sB2[i] = gB2[i];
    for (int i = tid; i < OUTD; i += THREADS) sB3[i] = gB3[i];
    __syncthreads();

    for (int tile = blockIdx.x; tile < numTiles; tile += gridDim.x) {

        // ---------- phase 0: load input tile (cols 0..63 -> A fp16) ----------
        {
            int row = tid >> 3, q = tid & 7;       // 8 threads per row, 8 cols each
            long long grow = (long long)tile * TBR + row;
            if (grow < (long long)Bsz) {
                const float* ip = gIn + (size_t)grow * IN_DIM;
                #pragma unroll
                for (int j = 0; j < 4; ++j) {
                    float a = ip[q * 8 + 2 * j], b = ip[q * 8 + 2 * j + 1];
                    uint32_t o = swoff(row, q * 8 + 2 * j, 128);
                    *(uint32_t*)(smc + OFF_AH + o) = pack2h(a, b);
                }
                if (q == 0) {
                    float dv = ip[64];
                    sDim[row] = dv;
                    int di = (int)dv; di = di < 0 ? 0 : (di > 15 ? 15 : di);
                    sSc[row] = gScaleTab[di];
                }
            } else {
                #pragma unroll
                for (int j = 0; j < 4; ++j) {
                    uint32_t o = swoff(row, q * 8 + 2 * j, 128);
                    *(uint32_t*)(smc + OFF_AH + o) = 0;
                }
                if (q == 0) { sDim[row] = 0.f; sSc[row] = OUTD; }
            }
        }
        __syncthreads();

        // ---------- GEMM1: [64x128] = A[64x64] @ W1^T (warp: 32r x 16c) ----------
        float acc1[2][2][4];
        #pragma unroll
        for (int mi = 0; mi < 2; ++mi)
            #pragma unroll
            for (int ni = 0; ni < 2; ++ni)
                #pragma unroll
                for (int d = 0; d < 4; ++d) acc1[mi][ni][d] = 0.f;
        #pragma unroll
        for (int ks = 0; ks < 4; ++ks) {
            uint32_t Ah[2][4], Bh[4], Bl[4];
            #pragma unroll
            for (int mi = 0; mi < 2; ++mi) {
                int r = wM * 32 + mi * 16 + (lane & 15);
                uint32_t kch = (uint32_t)(ks * 2 + (lane >> 4));
                uint32_t o = (uint32_t)(r * 128) + ((kch ^ (uint32_t)(r & 7)) << 4);
                ldsm4(Ah[mi], sb + OFF_AH + o);
            }
            {
                int n = wN * 16 + ((lane >> 4) << 3) + (lane & 7);
                uint32_t kch = (uint32_t)(ks * 2 + ((lane >> 3) & 1));
                uint32_t o = (uint32_t)(n * 128) + ((kch ^ (uint32_t)(n & 7)) << 4);
                ldsm4(Bh, sb + OFF_W1H + o);
                ldsm4(Bl, sb + OFF_W1L + o);
            }
            #pragma unroll
            for (int mi = 0; mi < 2; ++mi)
                #pragma unroll
                for (int h = 0; h < 2; ++h) {
                    mmah(acc1[mi][h], Ah[mi], Bh[h*2], Bh[h*2+1]);
                    mmah(acc1[mi][h], Ah[mi], Bl[h*2], Bl[h*2+1]);
                }
        }
        // epilogue 1: bias + exact dim-column correction + relu -> X1 fp16
        #pragma unroll
        for (int mi = 0; mi < 2; ++mi) {
            int r0 = wM * 32 + mi * 16 + (lane >> 2), r1 = r0 + 8;
            float d0 = sDim[r0], d1 = sDim[r1];
            #pragma unroll
            for (int ni = 0; ni < 2; ++ni) {
                int c0 = wN * 16 + ni * 8 + ((lane & 3) << 1);
                float bb0 = sB1[c0], bb1 = sB1[c0+1];
                float w0 = sC64[c0], w1 = sC64[c0+1];
                float v00 = fmaxf(acc1[mi][ni][0] + bb0 + d0 * w0, 0.f);
                float v01 = fmaxf(acc1[mi][ni][1] + bb1 + d0 * w1, 0.f);
                float v10 = fmaxf(acc1[mi][ni][2] + bb0 + d1 * w0, 0.f);
                float v11 = fmaxf(acc1[mi][ni][3] + bb1 + d1 * w1, 0.f);
                uint32_t o0 = swoff(r0, c0, 256), o1 = swoff(r1, c0, 256);
                *(uint32_t*)(smc + OFF_X1H + o0) = pack2h(v00, v01);
                *(uint32_t*)(smc + OFF_X1H + o1) = pack2h(v10, v11);
            }
        }
        __syncthreads();

        // ---------- GEMM2: [64x64] = X1[64x128] @ W2^T (warp: 32r x 8c) ----------
        float acc2[2][4];
        #pragma unroll
        for (int mi = 0; mi < 2; ++mi)
            #pragma unroll
            for (int d = 0; d < 4; ++d) acc2[mi][d] = 0.f;
        #pragma unroll
        for (int ks2 = 0; ks2 < 4; ++ks2) {
            // B: one ldsm4 covers TWO ks steps (4 k-chunks of the same n8)
            uint32_t Bh[4], Bl[4];
            {
                int n = wN * 8 + (lane & 7);
                uint32_t kch = (uint32_t)(ks2 * 4 + (lane >> 3));
                uint32_t o = (uint32_t)(n * 256) + ((kch ^ (uint32_t)(n & 7)) << 4);
                ldsm4(Bh, sb + OFF_W2H + o);
                ldsm4(Bl, sb + OFF_W2L + o);
            }
            #pragma unroll
            for (int s = 0; s < 2; ++s) {
                int ks = ks2 * 2 + s;
                uint32_t Ah[2][4];
                #pragma unroll
                for (int mi = 0; mi < 2; ++mi) {
                    int r = wM * 32 + mi * 16 + (lane & 15);
                    uint32_t kch = (uint32_t)(ks * 2 + (lane >> 4));
                    uint32_t o = (uint32_t)(r * 256) + ((kch ^ (uint32_t)(r & 7)) << 4);
                    ldsm4(Ah[mi], sb + OFF_X1H + o);
                }
                #pragma unroll
                for (int mi = 0; mi < 2; ++mi) {
                    mmah(acc2[mi], Ah[mi], Bh[s*2], Bh[s*2+1]);
                    mmah(acc2[mi], Ah[mi], Bl[s*2], Bl[s*2+1]);
                }
            }
        }
        // epilogue 2 -> X2 fp16
        #pragma unroll
        for (int mi = 0; mi < 2; ++mi) {
            int r0 = wM * 32 + mi * 16 + (lane >> 2), r1 = r0 + 8;
            int c0 = wN * 8 + ((lane & 3) << 1);
            float bb0 = sB2[c0], bb1 = sB2[c0+1];
            float v00 = fmaxf(acc2[mi][0] + bb0, 0.f);
            float v01 = fmaxf(acc2[mi][1] + bb1, 0.f);
            float v10 = fmaxf(acc2[mi][2] + bb0, 0.f);
            float v11 = fmaxf(acc2[mi][3] + bb1, 0.f);
            uint32_t o0 = swoff(r0, c0, 128), o1 = swoff(r1, c0, 128);
            *(uint32_t*)(smc + OFF_X2H + o0) = pack2h(v00, v01);
            *(uint32_t*)(smc + OFF_X2H + o1) = pack2h(v10, v11);
        }
        __syncthreads();

        // ---------- GEMM3: [64x256] = X2[64x64] @ W3^T (warp: 32r x 32c) ----------
        float acc3[2][4][4];
        #pragma unroll
        for (int mi = 0; mi < 2; ++mi)
            #pragma unroll
            for (int ni = 0; ni < 4; ++ni)
                #pragma unroll
                for (int d = 0; d < 4; ++d) acc3[mi][ni][d] = 0.f;
        #pragma unroll
        for (int ks = 0; ks < 4; ++ks) {
            uint32_t Ah[2][4];
            #pragma unroll
            for (int mi = 0; mi < 2; ++mi) {
                int r = wM * 32 + mi * 16 + (lane & 15);
                uint32_t kch = (uint32_t)(ks * 2 + (lane >> 4));
                uint32_t o = (uint32_t)(r * 128) + ((kch ^ (uint32_t)(r & 7)) << 4);
                ldsm4(Ah[mi], sb + OFF_X2H + o);
            }
            #pragma unroll
            for (int np = 0; np < 2; ++np) {
                uint32_t Bh[4], Bl[4];
                int n = wN * 32 + np * 16 + ((lane >> 4) << 3) + (lane & 7);
                uint32_t kch = (uint32_t)(ks * 2 + ((lane >> 3) & 1));
                uint32_t o = (uint32_t)(n * 128) + ((kch ^ (uint32_t)(n & 7)) << 4);
                ldsm4(Bh, sb + OFF_W3H + o);
                ldsm4(Bl, sb + OFF_W3L + o);
                #pragma unroll
                for (int mi = 0; mi < 2; ++mi)
                    #pragma unroll
                    for (int h = 0; h < 2; ++h) {
                        int ni = np * 2 + h;
                        mmah(acc3[mi][ni], Ah[mi], Bh[h*2], Bh[h*2+1]);
                        mmah(acc3[mi][ni], Ah[mi], Bl[h*2], Bl[h*2+1]);
                    }
            }
        }

        // ---------- epilogue 3: bias + masked softmax + stores ----------
        {
            #pragma unroll
            for (int mi = 0; mi < 2; ++mi)
                #pragma unroll
                for (int h = 0; h < 2; ++h) {
                    int r = wM * 32 + mi * 16 + (lane >> 2) + h * 8;
                    int scale = sSc[r];
                    float m = -3.4e38f;
                    #pragma unroll
                    for (int ni = 0; ni < 4; ++ni) {
                        int c0 = wN * 32 + ni * 8 + ((lane & 3) << 1);
                        float v0 = acc3[mi][ni][h*2]   + sB3[c0];
                        float v1 = acc3[mi][ni][h*2+1] + sB3[c0+1];
                        acc3[mi][ni][h*2]   = v0;
                        acc3[mi][ni][h*2+1] = v1;
                        if (c0     < scale) m = fmaxf(m, v0);
                        if (c0 + 1 < scale) m = fmaxf(m, v1);
                    }
                    m = fmaxf(m, __shfl_xor_sync(0xffffffffu, m, 1));
                    m = fmaxf(m, __shfl_xor_sync(0xffffffffu, m, 2));
                    if ((lane & 3) == 0) sPMax[wN * 64 + r] = m;
                }
            __syncthreads();
            #pragma unroll
            for (int mi = 0; mi < 2; ++mi)
                #pragma unroll
                for (int h = 0; h < 2; ++h) {
                    int r = wM * 32 + mi * 16 + (lane >> 2) + h * 8;
                    int scale = sSc[r];
                    float gm = -3.4e38f;
                    #pragma unroll
                    for (int w = 0; w < 8; ++w)
                        gm = fmaxf(gm, sPMax[w * 64 + r]);
                    float s = 0.f;
                    #pragma unroll
                    for (int ni = 0; ni < 4; ++ni) {
                        int c0 = wN * 32 + ni * 8 + ((lane & 3) << 1);
                        float e0 = (c0     < scale) ? __expf(acc3[mi][ni][h*2]   - gm) : 0.f;
                        float e1 = (c0 + 1 < scale) ? __expf(acc3[mi][ni][h*2+1] - gm) : 0.f;
                        acc3[mi][ni][h*2]   = e0;
                        acc3[mi][ni][h*2+1] = e1;
                        s += e0 + e1;
                    }
                    s += __shfl_xor_sync(0xffffffffu, s, 1);
                    s += __shfl_xor_sync(0xffffffffu, s, 2);
                    if ((lane & 3) == 0) sPSum[wN * 64 + r] = s;
                }
            __syncthreads();
            long long rowG0 = (long long)tile * TBR;
            #pragma unroll
            for (int mi = 0; mi < 2; ++mi)
                #pragma unroll
                for (int h = 0; h < 2; ++h) {
                    int r = wM * 32 + mi * 16 + (lane >> 2) + h * 8;
                    long long grow = rowG0 + r;
                    float ssum = 0.f;
                    #pragma unroll
                    for (int w = 0; w < 8; ++w)
                        ssum += sPSum[w * 64 + r];
                    float inv = 1.f / ssum;
                    if (grow < (long long)Bsz) {
                        float* po = gProbs + (size_t)grow * OUTD;
                        #pragma unroll
                        for (int ni = 0; ni < 4; ++ni) {
                            int c0 = wN * 32 + ni * 8 + ((lane & 3) << 1);
                            float2 t;
                            t.x = acc3[mi][ni][h*2]   * inv;
                            t.y = acc3[mi][ni][h*2+1] * inv;
                            *(float2*)(po + c0) = t;
                        }
                    }
                }
            // mask output (coalesced)
            if (gMask) {
                #pragma unroll
                for (int i = 0; i < 8; ++i) {
                    int g = tid + THREADS * i;
                    int row = g >> 6, c4 = g & 63;
                    long long grow = rowG0 + row;
                    if (grow < (long long)Bsz) {
                        int sc = sSc[row];
                        int c0 = c4 * 4;
                        float4 t;
                        t.x = (c0     < sc) ? 1.f : 0.f;
                        t.y = (c0 + 1 < sc) ? 1.f : 0.f;
                        t.z = (c0 + 2 < sc) ? 1.f : 0.f;
                        t.w = (c0 + 3 < sc) ? 1.f : 0.f;
                        *(float4*)(gMask + (size_t)grow * OUTD + c0) = t;
                    }
                }
            }
        }
        __syncthreads();   // protect sSc/sDim/A/X buffers before next tile
    }
}

extern "C" void kernel_launch(void* const* d_in, const int* in_sizes, int n_in,
                              void* d_out, int out_size)
{
    const float* gIn    = (const float*)d_in[0];
    const int*   gScale = (const int*)  d_in[1];
    const float* gW1    = (const float*)d_in[2];
    const float* gB1    = (const float*)d_in[3];
    const float* gW2    = (const float*)d_in[4];
    const float* gB2    = (const float*)d_in[5];
    const float* gW3    = (const float*)d_in[6];
    const float* gB3    = (const float*)d_in[7];

    int Bsz = in_sizes[0] / IN_DIM;
    int numTiles = (Bsz + TBR - 1) / TBR;

    float* gProbs = (float*)d_out;
    float* gMask  = nullptr;
    long long need2 = 2LL * Bsz * OUTD;
    if ((long long)out_size >= need2)
        gMask = gProbs + (size_t)Bsz * OUTD;

    cudaFuncSetAttribute(policy_mma_kernel,
                         cudaFuncAttributeMaxDynamicSharedMemorySize, SMEM_BYTES);

    int smCount = 148;
    cudaDeviceGetAttribute(&smCount, cudaDevAttrMultiProcessorCount, 0);
    int grid = numTiles < smCount ? numTiles : smCount;

    policy_mma_kernel<<<grid, THREADS, SMEM_BYTES>>>(
        gIn, gScale, gW1, gB1, gW2, gB2, gW3, gB3,
        gProbs, gMask, Bsz, numTiles);
}

// round 14
// speedup vs baseline: 1.3077x; 1.0726x over previous
#include <cuda_runtime.h>
#include <cuda_fp16.h>
#include <cstdint>

#define THREADS 512
#define TBR     64
#define IN_DIM  65
#define H1      128
#define H2      64
#define OUTD    256

// ---------------- shared weight region ----------------
#define OFF_W1H  0        // [128][64] fp16 swz, 16384
#define OFF_W1L  16384
#define OFF_W2H  32768    // [64][128] fp16 swz, 16384
#define OFF_W2L  49152
#define OFF_W3H  65536    // [256][64] fp16 swz, 32768
#define OFF_W3L  98304
#define OFF_B1   131072   // 512
#define OFF_B2   131584   // 256
#define OFF_B3   131840   // 1024
#define OFF_C64  132864   // 512 (W1 col 64, fp32)
// ---------------- per-group region (g = 0/1) ----------------
#define OFF_GRP  133376
#define GRP_SZ   35328
#define GA       0        // [64][64]  fp16 swz, 8192
#define GX1      8192     // [64][128] fp16 swz, 16384
#define GX2      24576    // [64][64]  fp16 swz, 8192
#define GDIM     32768    // 256
#define GSC      33024    // 256
#define GPMAX    33280    // 4*64*4 = 1024
#define GPSUM    34304    // 1024
#define SMEM_BYTES (OFF_GRP + 2*GRP_SZ)   // 204032

__device__ __forceinline__ uint32_t smem_u32(const void* p) {
    uint32_t a;
    asm("{ .reg .u64 t; cvta.to.shared.u64 t, %1; cvt.u32.u64 %0, t; }" : "=r"(a) : "l"(p));
    return a;
}
__device__ __forceinline__ uint32_t swoff(int r, int k, int sB) {
    return (uint32_t)(r * sB) + (uint32_t)((((k >> 3) ^ (r & 7)) << 4) + ((k & 7) << 1));
}
__device__ __forceinline__ float h16rt(float x) {
    return __half2float(__float2half_rn(x));
}
__device__ __forceinline__ uint32_t pack2h(float a, float b) {
    __half2 t = __floats2half2_rn(a, b);
    return *(uint32_t*)&t;
}
__device__ __forceinline__ void ldsm4(uint32_t (&a)[4], uint32_t addr) {
    asm volatile("ldmatrix.sync.aligned.m8n8.x4.shared.b16 {%0,%1,%2,%3}, [%4];"
        : "=r"(a[0]), "=r"(a[1]), "=r"(a[2]), "=r"(a[3]) : "r"(addr));
}
__device__ __forceinline__ void mmah(float (&d)[4], const uint32_t (&a)[4],
                                     uint32_t b0, uint32_t b1) {
    asm volatile("mma.sync.aligned.m16n8k16.row.col.f32.f16.f16.f32 "
        "{%0,%1,%2,%3},{%4,%5,%6,%7},{%8,%9},{%0,%1,%2,%3};"
        : "+f"(d[0]), "+f"(d[1]), "+f"(d[2]), "+f"(d[3])
        : "r"(a[0]), "r"(a[1]), "r"(a[2]), "r"(a[3]), "r"(b0), "r"(b1));
}
#define GBAR(id) asm volatile("bar.sync %0, 256;" :: "r"(id) : "memory")

__global__ void __launch_bounds__(THREADS, 1)
policy_mma_kernel(const float* __restrict__ gIn, const int* __restrict__ gScaleTab,
                  const float* __restrict__ gW1, const float* __restrict__ gB1,
                  const float* __restrict__ gW2, const float* __restrict__ gB2,
                  const float* __restrict__ gW3, const float* __restrict__ gB3,
                  float* __restrict__ gProbs, float* __restrict__ gMask,
                  int Bsz, int numTiles)
{
    extern __shared__ char smc[];
    const int tid  = threadIdx.x;
    const int lane = tid & 31;
    const int wid  = tid >> 5;
    const int g    = wid >> 3;         // pipeline group 0/1
    const int gwid = wid & 7;          // warp within group
    const int gtid = tid & 255;        // thread within group
    const int wM   = gwid >> 2;        // 0..1 (32 rows)
    const int wN   = gwid & 3;         // 0..3
    const int bar  = g + 1;            // named barrier id
    const uint32_t sb = smem_u32(smc);

    char* gsm = smc + OFF_GRP + g * GRP_SZ;
    const uint32_t gbu = sb + OFF_GRP + (uint32_t)g * GRP_SZ;

    float* sB1  = (float*)(smc + OFF_B1);
    float* sB2  = (float*)(smc + OFF_B2);
    float* sB3  = (float*)(smc + OFF_B3);
    float* sC64 = (float*)(smc + OFF_C64);
    float* sDim = (float*)(gsm + GDIM);
    int*   sSc  = (int*)  (gsm + GSC);
    float* sPMax = (float*)(gsm + GPMAX);
    float* sPSum = (float*)(gsm + GPSUM);

    // ---- one-time: stage weights as fp16 hi/lo (all 512 threads) ----
    for (int idx = tid; idx < H1 * 64; idx += THREADS) {          // W1[:, 0:64]
        int n = idx >> 6, k = idx & 63;
        float x = gW1[n * IN_DIM + k];
        float h = h16rt(x);
        uint32_t o = swoff(n, k, 128);
        *(__half*)(smc + OFF_W1H + o) = __float2half_rn(h);
        *(__half*)(smc + OFF_W1L + o) = __float2half_rn(x - h);
    }
    for (int n = tid; n < H1; n += THREADS) sC64[n] = gW1[n * IN_DIM + 64];
    for (int idx = tid; idx < H2 * H1; idx += THREADS) {          // W2 [64][128]
        int n = idx >> 7, k = idx & 127;
        float x = gW2[idx];
        float h = h16rt(x);
        uint32_t o = swoff(n, k, 256);
        *(__half*)(smc + OFF_W2H + o) = __float2half_rn(h);
        *(__half*)(smc + OFF_W2L + o) = __float2half_rn(x - h);
    }
    for (int idx = tid; idx < OUTD * H2; idx += THREADS) {        // W3 [256][64]
        int n = idx >> 6, k = idx & 63;
        float x = gW3[idx];
        float h = h16rt(x);
        uint32_t o = swoff(n, k, 128);
        *(__half*)(smc + OFF_W3H + o) = __float2half_rn(h);
        *(__half*)(smc + OFF_W3L + o) = __float2half_rn(x - h);
    }
    for (int i = tid; i < H1; i += THREADS)   sB1[i] = gB1[i];
    for (int i = tid; i < H2; i += THREADS)   sB2[i] = gB2[i];
    for (int i = tid; i < OUTD; i += THREADS) sB3[i] = gB3[i];
    __syncthreads();   // the ONLY full-CTA barrier

    for (int tile = blockIdx.x * 2 + g; tile < numTiles; tile += gridDim.x * 2) {

        // ---------- phase 0: load input tile (cols 0..63 -> A fp16) ----------
        {
            int row = gtid >> 2, q = gtid & 3;     // 4 threads/row, 16 cols each
            long long grow = (long long)tile * TBR + row;
            if (grow < (long long)Bsz) {
                const float* ip = gIn + (size_t)grow * IN_DIM;
                #pragma unroll
                for (int j = 0; j < 8; ++j) {
                    float a = ip[q * 16 + 2 * j], b = ip[q * 16 + 2 * j + 1];
                    uint32_t o = swoff(row, q * 16 + 2 * j, 128);
                    *(uint32_t*)(gsm + GA + o) = pack2h(a, b);
                }
                if (q == 0) {
                    float dv = ip[64];
                    sDim[row] = dv;
                    int di = (int)dv; di = di < 0 ? 0 : (di > 15 ? 15 : di);
                    sSc[row] = gScaleTab[di];
                }
            } else {
                #pragma unroll
                for (int j = 0; j < 8; ++j) {
                    uint32_t o = swoff(row, q * 16 + 2 * j, 128);
                    *(uint32_t*)(gsm + GA + o) = 0;
                }
                if (q == 0) { sDim[row] = 0.f; sSc[row] = OUTD; }
            }
        }
        GBAR(bar);

        // ---------- GEMM1: [64x128] = A @ W1^T (warp: 32r x 32c) ----------
        float acc1[2][4][4];
        #pragma unroll
        for (int mi = 0; mi < 2; ++mi)
            #pragma unroll
            for (int ni = 0; ni < 4; ++ni)
                #pragma unroll
                for (int d = 0; d < 4; ++d) acc1[mi][ni][d] = 0.f;
        #pragma unroll
        for (int ks = 0; ks < 4; ++ks) {
            uint32_t Ah[2][4], Bh[2][4], Bl[2][4];
            #pragma unroll
            for (int mi = 0; mi < 2; ++mi) {
                int r = wM * 32 + mi * 16 + (lane & 15);
                uint32_t kch = (uint32_t)(ks * 2 + (lane >> 4));
                uint32_t o = (uint32_t)(r * 128) + ((kch ^ (uint32_t)(r & 7)) << 4);
                ldsm4(Ah[mi], gbu + GA + o);
            }
            #pragma unroll
            for (int np = 0; np < 2; ++np) {
                int n = wN * 32 + np * 16 + ((lane >> 4) << 3) + (lane & 7);
                uint32_t kch = (uint32_t)(ks * 2 + ((lane >> 3) & 1));
                uint32_t o = (uint32_t)(n * 128) + ((kch ^ (uint32_t)(n & 7)) << 4);
                ldsm4(Bh[np], sb + OFF_W1H + o);
                ldsm4(Bl[np], sb + OFF_W1L + o);
            }
            #pragma unroll
            for (int mi = 0; mi < 2; ++mi)
                #pragma unroll
                for (int np = 0; np < 2; ++np)
                    #pragma unroll
                    for (int h = 0; h < 2; ++h) {
                        int ni = np * 2 + h;
                        mmah(acc1[mi][ni], Ah[mi], Bh[np][h*2], Bh[np][h*2+1]);
                        mmah(acc1[mi][ni], Ah[mi], Bl[np][h*2], Bl[np][h*2+1]);
                    }
        }
        // epilogue 1: bias + dim-column correction + relu -> X1 fp16
        #pragma unroll
        for (int mi = 0; mi < 2; ++mi) {
            int r0 = wM * 32 + mi * 16 + (lane >> 2), r1 = r0 + 8;
            float d0 = sDim[r0], d1 = sDim[r1];
            #pragma unroll
            for (int ni = 0; ni < 4; ++ni) {
                int c0 = wN * 32 + ni * 8 + ((lane & 3) << 1);
                float bb0 = sB1[c0], bb1 = sB1[c0+1];
                float w0 = sC64[c0], w1 = sC64[c0+1];
                float v00 = fmaxf(acc1[mi][ni][0] + bb0 + d0 * w0, 0.f);
                float v01 = fmaxf(acc1[mi][ni][1] + bb1 + d0 * w1, 0.f);
                float v10 = fmaxf(acc1[mi][ni][2] + bb0 + d1 * w0, 0.f);
                float v11 = fmaxf(acc1[mi][ni][3] + bb1 + d1 * w1, 0.f);
                uint32_t o0 = swoff(r0, c0, 256), o1 = swoff(r1, c0, 256);
                *(uint32_t*)(gsm + GX1 + o0) = pack2h(v00, v01);
                *(uint32_t*)(gsm + GX1 + o1) = pack2h(v10, v11);
            }
        }
        GBAR(bar);

        // ---------- GEMM2: [64x64] = X1 @ W2^T (warp: 32r x 16c) ----------
        float acc2[2][2][4];
        #pragma unroll
        for (int mi = 0; mi < 2; ++mi)
            #pragma unroll
            for (int ni = 0; ni < 2; ++ni)
                #pragma unroll
                for (int d = 0; d < 4; ++d) acc2[mi][ni][d] = 0.f;
        #pragma unroll
        for (int ks = 0; ks < 8; ++ks) {
            uint32_t Ah[2][4], Bh[4], Bl[4];
            #pragma unroll
            for (int mi = 0; mi < 2; ++mi) {
                int r = wM * 32 + mi * 16 + (lane & 15);
                uint32_t kch = (uint32_t)(ks * 2 + (lane >> 4));
                uint32_t o = (uint32_t)(r * 256) + ((kch ^ (uint32_t)(r & 7)) << 4);
                ldsm4(Ah[mi], gbu + GX1 + o);
            }
            {
                int n = wN * 16 + ((lane >> 4) << 3) + (lane & 7);
                uint32_t kch = (uint32_t)(ks * 2 + ((lane >> 3) & 1));
                uint32_t o = (uint32_t)(n * 256) + ((kch ^ (uint32_t)(n & 7)) << 4);
                ldsm4(Bh, sb + OFF_W2H + o);
                ldsm4(Bl, sb + OFF_W2L + o);
            }
            #pragma unroll
            for (int mi = 0; mi < 2; ++mi)
                #pragma unroll
                for (int h = 0; h < 2; ++h) {
                    mmah(acc2[mi][h], Ah[mi], Bh[h*2], Bh[h*2+1]);
                    mmah(acc2[mi][h], Ah[mi], Bl[h*2], Bl[h*2+1]);
                }
        }
        // epilogue 2 -> X2 fp16
        #pragma unroll
        for (int mi = 0; mi < 2; ++mi) {
            int r0 = wM * 32 + mi * 16 + (lane >> 2), r1 = r0 + 8;
            #pragma unroll
            for (int ni = 0; ni < 2; ++ni) {
                int c0 = wN * 16 + ni * 8 + ((lane & 3) << 1);
                float bb0 = sB2[c0], bb1 = sB2[c0+1];
                float v00 = fmaxf(acc2[mi][ni][0] + bb0, 0.f);
                float v01 = fmaxf(acc2[mi][ni][1] + bb1, 0.f);
                float v10 = fmaxf(acc2[mi][ni][2] + bb0, 0.f);
                float v11 = fmaxf(acc2[mi][ni][3] + bb1, 0.f);
                uint32_t o0 = swoff(r0, c0, 128), o1 = swoff(r1, c0, 128);
                *(uint32_t*)(gsm + GX2 + o0) = pack2h(v00, v01);
                *(uint32_t*)(gsm + GX2 + o1) = pack2h(v10, v11);
            }
        }
        GBAR(bar);

        // ---------- GEMM3: [64x256] = X2 @ W3^T (warp: 32r x 64c) ----------
        float acc3[2][8][4];
        #pragma unroll
        for (int mi = 0; mi < 2; ++mi)
            #pragma unroll
            for (int ni = 0; ni < 8; ++ni)
                #pragma unroll
                for (int d = 0; d < 4; ++d) acc3[mi][ni][d] = 0.f;
        #pragma unroll
        for (int ks = 0; ks < 4; ++ks) {
            uint32_t Ah[2][4];
            #pragma unroll
            for (int mi = 0; mi < 2; ++mi) {
                int r = wM * 32 + mi * 16 + (lane & 15);
                uint32_t kch = (uint32_t)(ks * 2 + (lane >> 4));
                uint32_t o = (uint32_t)(r * 128) + ((kch ^ (uint32_t)(r & 7)) << 4);
                ldsm4(Ah[mi], gbu + GX2 + o);
            }
            #pragma unroll
            for (int np = 0; np < 4; ++np) {
                uint32_t Bh[4], Bl[4];
                int n = wN * 64 + np * 16 + ((lane >> 4) << 3) + (lane & 7);
                uint32_t kch = (uint32_t)(ks * 2 + ((lane >> 3) & 1));
                uint32_t o = (uint32_t)(n * 128) + ((kch ^ (uint32_t)(n & 7)) << 4);
                ldsm4(Bh, sb + OFF_W3H + o);
                ldsm4(Bl, sb + OFF_W3L + o);
                #pragma unroll
                for (int mi = 0; mi < 2; ++mi)
                    #pragma unroll
                    for (int h = 0; h < 2; ++h) {
                        int ni = np * 2 + h;
                        mmah(acc3[mi][ni], Ah[mi], Bh[h*2], Bh[h*2+1]);
                        mmah(acc3[mi][ni], Ah[mi], Bl[h*2], Bl[h*2+1]);
                    }
            }
        }

        // ---------- epilogue 3: bias + masked softmax + stores ----------
        {
            #pragma unroll
            for (int mi = 0; mi < 2; ++mi)
                #pragma unroll
                for (int h = 0; h < 2; ++h) {
                    int r = wM * 32 + mi * 16 + (lane >> 2) + h * 8;
                    int scale = sSc[r];
                    float m = -3.4e38f;
                    #pragma unroll
                    for (int ni = 0; ni < 8; ++ni) {
                        int c0 = wN * 64 + ni * 8 + ((lane & 3) << 1);
                        float v0 = acc3[mi][ni][h*2]   + sB3[c0];
                        float v1 = acc3[mi][ni][h*2+1] + sB3[c0+1];
                        acc3[mi][ni][h*2]   = v0;
                        acc3[mi][ni][h*2+1] = v1;
                        if (c0     < scale) m = fmaxf(m, v0);
                        if (c0 + 1 < scale) m = fmaxf(m, v1);
                    }
                    m = fmaxf(m, __shfl_xor_sync(0xffffffffu, m, 1));
                    m = fmaxf(m, __shfl_xor_sync(0xffffffffu, m, 2));
                    if ((lane & 3) == 0) sPMax[wN * 64 + r] = m;
                }
            GBAR(bar);
            #pragma unroll
            for (int mi = 0; mi < 2; ++mi)
                #pragma unroll
                for (int h = 0; h < 2; ++h) {
                    int r = wM * 32 + mi * 16 + (lane >> 2) + h * 8;
                    int scale = sSc[r];
                    float gm = fmaxf(fmaxf(sPMax[r], sPMax[64 + r]),
                                     fmaxf(sPMax[128 + r], sPMax[192 + r]));
                    float s = 0.f;
                    #pragma unroll
                    for (int ni = 0; ni < 8; ++ni) {
                        int c0 = wN * 64 + ni * 8 + ((lane & 3) << 1);
                        float e0 = (c0     < scale) ? __expf(acc3[mi][ni][h*2]   - gm) : 0.f;
                        float e1 = (c0 + 1 < scale) ? __expf(acc3[mi][ni][h*2+1] - gm) : 0.f;
                        acc3[mi][ni][h*2]   = e0;
                        acc3[mi][ni][h*2+1] = e1;
                        s += e0 + e1;
                    }
                    s += __shfl_xor_sync(0xffffffffu, s, 1);
                    s += __shfl_xor_sync(0xffffffffu, s, 2);
                    if ((lane & 3) == 0) sPSum[wN * 64 + r] = s;
                }
            GBAR(bar);
            long long rowG0 = (long long)tile * TBR;
            #pragma unroll
            for (int mi = 0; mi < 2; ++mi)
                #pragma unroll
                for (int h = 0; h < 2; ++h) {
                    int r = wM * 32 + mi * 16 + (lane >> 2) + h * 8;
                    long long grow = rowG0 + r;
                    float inv = 1.f / (sPSum[r] + sPSum[64 + r] +
                                       sPSum[128 + r] + sPSum[192 + r]);
                    if (grow < (long long)Bsz) {
                        float* po = gProbs + (size_t)grow * OUTD;
                        #pragma unroll
                        for (int ni = 0; ni < 8; ++ni) {
                            int c0 = wN * 64 + ni * 8 + ((lane & 3) << 1);
                            float2 t;
                            t.x = acc3[mi][ni][h*2]   * inv;
                            t.y = acc3[mi][ni][h*2+1] * inv;
                            *(float2*)(po + c0) = t;
                        }
                    }
                }
            // mask output (coalesced, group threads)
            if (gMask) {
                #pragma unroll
                for (int i = 0; i < 16; ++i) {
                    int gg = gtid + 256 * i;
                    int row = gg >> 6, c4 = gg & 63;
                    long long grow = rowG0 + row;
                    if (grow < (long long)Bsz) {
                        int sc = sSc[row];
                        int c0 = c4 * 4;
                        float4 t;
                        t.x = (c0     < sc) ? 1.f : 0.f;
                        t.y = (c0 + 1 < sc) ? 1.f : 0.f;
                        t.z = (c0 + 2 < sc) ? 1.f : 0.f;
                        t.w = (c0 + 3 < sc) ? 1.f : 0.f;
                        *(float4*)(gMask + (size_t)grow * OUTD + c0) = t;
                    }
                }
            }
        }
        GBAR(bar);   // protect group buffers before next tile
    }
}

extern "C" void kernel_launch(void* const* d_in, const int* in_sizes, int n_in,
                              void* d_out, int out_size)
{
    const float* gIn    = (const float*)d_in[0];
    const int*   gScale = (const int*)  d_in[1];
    const float* gW1    = (const float*)d_in[2];
    const float* gB1    = (const float*)d_in[3];
    const float* gW2    = (const float*)d_in[4];
    const float* gB2    = (const float*)d_in[5];
    const float* gW3    = (const float*)d_in[6];
    const float* gB3    = (const float*)d_in[7];

    int Bsz = in_sizes[0] / IN_DIM;
    int numTiles = (Bsz + TBR - 1) / TBR;

    float* gProbs = (float*)d_out;
    float* gMask  = nullptr;
    long long need2 = 2LL * Bsz * OUTD;
    if ((long long)out_size >= need2)
        gMask = gProbs + (size_t)Bsz * OUTD;

    cudaFuncSetAttribute(policy_mma_kernel,
                         cudaFuncAttributeMaxDynamicSharedMemorySize, SMEM_BYTES);

    int smCount = 148;
    cudaDeviceGetAttribute(&smCount, cudaDevAttrMultiProcessorCount, 0);
    int streams = (numTiles + 1) / 2;
    int grid = streams < smCount ? streams : smCount;

    policy_mma_kernel<<<grid, THREADS, SMEM_BYTES>>>(
        gIn, gScale, gW1, gB1, gW2, gB2, gW3, gB3,
        gProbs, gMask, Bsz, numTiles);
}

// round 15
// speedup vs baseline: 1.3177x; 1.0077x over previous
#include <cuda_runtime.h>
#include <cuda_fp16.h>
#include <cstdint>

#define THREADS 512
#define TBR     128
#define IN_DIM  65
#define H1      128
#define H2      64
#define OUTD    256

// ---------------- smem byte offsets ----------------
#define OFF_W1H  0        // [128][64] fp16 swz, 16384
#define OFF_W1L  16384    // (unused by MMA now, kept for layout simplicity)
#define OFF_W2H  32768    // [64][128] fp16 swz, 16384
#define OFF_W2L  49152
#define OFF_W3H  65536    // [256][64] fp16 swz, 32768
#define OFF_W3L  98304
#define OFF_B1   131072   // 512
#define OFF_B2   131584   // 256
#define OFF_B3   131840   // 1024
#define OFF_C64  132864   // 512 (W1 col 64, fp32)
#define OFF_A    133376   // [128][64]  fp16 swz, 16384
#define OFF_X1   149760   // [128][128] fp16 swz, 32768  (133376+16384)
#define OFF_X2   182528   // [128][64]  fp16 swz, 16384
#define OFF_DIM  198912   // 512
#define OFF_SC   199424   // 512 (int)
#define OFF_PMAX 199936   // 4*128*4 = 2048
#define OFF_PSUM 201984   // 2048
#define SMEM_BYTES 204032

__device__ __forceinline__ uint32_t smem_u32(const void* p) {
    uint32_t a;
    asm("{ .reg .u64 t; cvta.to.shared.u64 t, %1; cvt.u32.u64 %0, t; }" : "=r"(a) : "l"(p));
    return a;
}
__device__ __forceinline__ uint32_t swoff(int r, int k, int sB) {
    return (uint32_t)(r * sB) + (uint32_t)((((k >> 3) ^ (r & 7)) << 4) + ((k & 7) << 1));
}
__device__ __forceinline__ float h16rt(float x) {
    return __half2float(__float2half_rn(x));
}
__device__ __forceinline__ uint32_t pack2h(float a, float b) {
    __half2 t = __floats2half2_rn(a, b);
    return *(uint32_t*)&t;
}
__device__ __forceinline__ void ldsm4(uint32_t (&a)[4], uint32_t addr) {
    asm volatile("ldmatrix.sync.aligned.m8n8.x4.shared.b16 {%0,%1,%2,%3}, [%4];"
        : "=r"(a[0]), "=r"(a[1]), "=r"(a[2]), "=r"(a[3]) : "r"(addr));
}
__device__ __forceinline__ void mmah(float (&d)[4], const uint32_t (&a)[4],
                                     uint32_t b0, uint32_t b1) {
    asm volatile("mma.sync.aligned.m16n8k16.row.col.f32.f16.f16.f32 "
        "{%0,%1,%2,%3},{%4,%5,%6,%7},{%8,%9},{%0,%1,%2,%3};"
        : "+f"(d[0]), "+f"(d[1]), "+f"(d[2]), "+f"(d[3])
        : "r"(a[0]), "r"(a[1]), "r"(a[2]), "r"(a[3]), "r"(b0), "r"(b1));
}

__global__ void __launch_bounds__(THREADS, 1)
policy_mma_kernel(const float* __restrict__ gIn, const int* __restrict__ gScaleTab,
                  const float* __restrict__ gW1, const float* __restrict__ gB1,
                  const float* __restrict__ gW2, const float* __restrict__ gB2,
                  const float* __restrict__ gW3, const float* __restrict__ gB3,
                  float* __restrict__ gProbs, float* __restrict__ gMask,
                  int Bsz, int numTiles)
{
    extern __shared__ char smc[];
    const int tid  = threadIdx.x;
    const int lane = tid & 31;
    const int wid  = tid >> 5;
    const int wM   = wid >> 2;     // 0..3 (32 rows each)
    const int wN   = wid & 3;      // 0..3
    const uint32_t sb = smem_u32(smc);

    float* sB1  = (float*)(smc + OFF_B1);
    float* sB2  = (float*)(smc + OFF_B2);
    float* sB3  = (float*)(smc + OFF_B3);
    float* sC64 = (float*)(smc + OFF_C64);
    float* sDim = (float*)(smc + OFF_DIM);
    int*   sSc  = (int*)  (smc + OFF_SC);
    float* sPMax = (float*)(smc + OFF_PMAX);
    float* sPSum = (float*)(smc + OFF_PSUM);

    // ---- one-time: stage weights (W1/W2 hi only; W3 hi+lo) ----
    for (int idx = tid; idx < H1 * 64; idx += THREADS) {          // W1[:, 0:64]
        int n = idx >> 6, k = idx & 63;
        float x = gW1[n * IN_DIM + k];
        *(__half*)(smc + OFF_W1H + swoff(n, k, 128)) = __float2half_rn(x);
    }
    for (int n = tid; n < H1; n += THREADS) sC64[n] = gW1[n * IN_DIM + 64];
    for (int idx = tid; idx < H2 * H1; idx += THREADS) {          // W2 [64][128]
        int n = idx >> 7, k = idx & 127;
        float x = gW2[idx];
        *(__half*)(smc + OFF_W2H + swoff(n, k, 256)) = __float2half_rn(x);
    }
    for (int idx = tid; idx < OUTD * H2; idx += THREADS) {        // W3 [256][64]
        int n = idx >> 6, k = idx & 63;
        float x = gW3[idx];
        float h = h16rt(x);
        uint32_t o = swoff(n, k, 128);
        *(__half*)(smc + OFF_W3H + o) = __float2half_rn(h);
        *(__half*)(smc + OFF_W3L + o) = __float2half_rn(x - h);
    }
    for (int i = tid; i < H1; i += THREADS)   sB1[i] = gB1[i];
    for (int i = tid; i < H2; i += THREADS)   sB2[i] = gB2[i];
    for (int i = tid; i < OUTD; i += THREADS) sB3[i] = gB3[i];
    __syncthreads();

    for (int tile = blockIdx.x; tile < numTiles; tile += gridDim.x) {

        // ---------- phase 0: load input tile (128 rows, cols 0..63 -> A fp16) ----------
        {
            int row = tid >> 2, q = tid & 3;      // 4 threads/row, 16 cols each
            long long grow = (long long)tile * TBR + row;
            if (grow < (long long)Bsz) {
                const float* ip = gIn + (size_t)grow * IN_DIM;
                #pragma unroll
                for (int j = 0; j < 8; ++j) {
                    float a = ip[q * 16 + 2 * j], b = ip[q * 16 + 2 * j + 1];
                    uint32_t o = swoff(row, q * 16 + 2 * j, 128);
                    *(uint32_t*)(smc + OFF_A + o) = pack2h(a, b);
                }
                if (q == 0) {
                    float dv = ip[64];
                    sDim[row] = dv;
                    int di = (int)dv; di = di < 0 ? 0 : (di > 15 ? 15 : di);
                    sSc[row] = gScaleTab[di];
                }
            } else {
                #pragma unroll
                for (int j = 0; j < 8; ++j) {
                    uint32_t o = swoff(row, q * 16 + 2 * j, 128);
                    *(uint32_t*)(smc + OFF_A + o) = 0;
                }
                if (q == 0) { sDim[row] = 0.f; sSc[row] = OUTD; }
            }
        }
        __syncthreads();

        // ---------- GEMM1: [128x128] = A @ W1^T (warp: 32r x 32c, hi only) ----------
        float acc1[2][4][4];
        #pragma unroll
        for (int mi = 0; mi < 2; ++mi)
            #pragma unroll
            for (int ni = 0; ni < 4; ++ni)
                #pragma unroll
                for (int d = 0; d < 4; ++d) acc1[mi][ni][d] = 0.f;
        #pragma unroll
        for (int ks = 0; ks < 4; ++ks) {
            uint32_t Ah[2][4], Bh[2][4];
            #pragma unroll
            for (int mi = 0; mi < 2; ++mi) {
                int r = wM * 32 + mi * 16 + (lane & 15);
                uint32_t kch = (uint32_t)(ks * 2 + (lane >> 4));
                uint32_t o = (uint32_t)(r * 128) + ((kch ^ (uint32_t)(r & 7)) << 4);
                ldsm4(Ah[mi], sb + OFF_A + o);
            }
            #pragma unroll
            for (int np = 0; np < 2; ++np) {
                int n = wN * 32 + np * 16 + ((lane >> 4) << 3) + (lane & 7);
                uint32_t kch = (uint32_t)(ks * 2 + ((lane >> 3) & 1));
                uint32_t o = (uint32_t)(n * 128) + ((kch ^ (uint32_t)(n & 7)) << 4);
                ldsm4(Bh[np], sb + OFF_W1H + o);
            }
            #pragma unroll
            for (int mi = 0; mi < 2; ++mi)
                #pragma unroll
                for (int np = 0; np < 2; ++np)
                    #pragma unroll
                    for (int h = 0; h < 2; ++h)
                        mmah(acc1[mi][np * 2 + h], Ah[mi], Bh[np][h*2], Bh[np][h*2+1]);
        }
        // epilogue 1: bias + dim-column correction + relu -> X1 fp16
        #pragma unroll
        for (int mi = 0; mi < 2; ++mi) {
            int r0 = wM * 32 + mi * 16 + (lane >> 2), r1 = r0 + 8;
            float d0 = sDim[r0], d1 = sDim[r1];
            #pragma unroll
            for (int ni = 0; ni < 4; ++ni) {
                int c0 = wN * 32 + ni * 8 + ((lane & 3) << 1);
                float bb0 = sB1[c0], bb1 = sB1[c0+1];
                float w0 = sC64[c0], w1 = sC64[c0+1];
                float v00 = fmaxf(acc1[mi][ni][0] + bb0 + d0 * w0, 0.f);
                float v01 = fmaxf(acc1[mi][ni][1] + bb1 + d0 * w1, 0.f);
                float v10 = fmaxf(acc1[mi][ni][2] + bb0 + d1 * w0, 0.f);
                float v11 = fmaxf(acc1[mi][ni][3] + bb1 + d1 * w1, 0.f);
                uint32_t o0 = swoff(r0, c0, 256), o1 = swoff(r1, c0, 256);
                *(uint32_t*)(smc + OFF_X1 + o0) = pack2h(v00, v01);
                *(uint32_t*)(smc + OFF_X1 + o1) = pack2h(v10, v11);
            }
        }
        __syncthreads();

        // ---------- GEMM2: [128x64] = X1 @ W2^T (warp: 32r x 16c, hi only) ----------
        float acc2[2][2][4];
        #pragma unroll
        for (int mi = 0; mi < 2; ++mi)
            #pragma unroll
            for (int ni = 0; ni < 2; ++ni)
                #pragma unroll
                for (int d = 0; d < 4; ++d) acc2[mi][ni][d] = 0.f;
        #pragma unroll
        for (int ks = 0; ks < 8; ++ks) {
            uint32_t Ah[2][4], Bh[4];
            #pragma unroll
            for (int mi = 0; mi < 2; ++mi) {
                int r = wM * 32 + mi * 16 + (lane & 15);
                uint32_t kch = (uint32_t)(ks * 2 + (lane >> 4));
                uint32_t o = (uint32_t)(r * 256) + ((kch ^ (uint32_t)(r & 7)) << 4);
                ldsm4(Ah[mi], sb + OFF_X1 + o);
            }
            {
                int n = wN * 16 + ((lane >> 4) << 3) + (lane & 7);
                uint32_t kch = (uint32_t)(ks * 2 + ((lane >> 3) & 1));
                uint32_t o = (uint32_t)(n * 256) + ((kch ^ (uint32_t)(n & 7)) << 4);
                ldsm4(Bh, sb + OFF_W2H + o);
            }
            #pragma unroll
            for (int mi = 0; mi < 2; ++mi)
                #pragma unroll
                for (int h = 0; h < 2; ++h)
                    mmah(acc2[mi][h], Ah[mi], Bh[h*2], Bh[h*2+1]);
        }
        // epilogue 2 -> X2 fp16
        #pragma unroll
        for (int mi = 0; mi < 2; ++mi) {
            int r0 = wM * 32 + mi * 16 + (lane >> 2), r1 = r0 + 8;
            #pragma unroll
            for (int ni = 0; ni < 2; ++ni) {
                int c0 = wN * 16 + ni * 8 + ((lane & 3) << 1);
                float bb0 = sB2[c0], bb1 = sB2[c0+1];
                float v00 = fmaxf(acc2[mi][ni][0] + bb0, 0.f);
                float v01 = fmaxf(acc2[mi][ni][1] + bb1, 0.f);
                float v10 = fmaxf(acc2[mi][ni][2] + bb0, 0.f);
                float v11 = fmaxf(acc2[mi][ni][3] + bb1, 0.f);
                uint32_t o0 = swoff(r0, c0, 128), o1 = swoff(r1, c0, 128);
                *(uint32_t*)(smc + OFF_X2 + o0) = pack2h(v00, v01);
                *(uint32_t*)(smc + OFF_X2 + o1) = pack2h(v10, v11);
            }
        }
        __syncthreads();

        // ---------- GEMM3: [128x256] = X2 @ W3^T (warp: 32r x 64c, hi+lo) ----------
        float acc3[2][8][4];
        #pragma unroll
        for (int mi = 0; mi < 2; ++mi)
            #pragma unroll
            for (int ni = 0; ni < 8; ++ni)
                #pragma unroll
                for (int d = 0; d < 4; ++d) acc3[mi][ni][d] = 0.f;
        #pragma unroll
        for (int ks = 0; ks < 4; ++ks) {
            uint32_t Ah[2][4];
            #pragma unroll
            for (int mi = 0; mi < 2; ++mi) {
                int r = wM * 32 + mi * 16 + (lane & 15);
                uint32_t kch = (uint32_t)(ks * 2 + (lane >> 4));
                uint32_t o = (uint32_t)(r * 128) + ((kch ^ (uint32_t)(r & 7)) << 4);
                ldsm4(Ah[mi], sb + OFF_X2 + o);
            }
            #pragma unroll
            for (int np = 0; np < 4; ++np) {
                uint32_t Bh[4], Bl[4];
                int n = wN * 64 + np * 16 + ((lane >> 4) << 3) + (lane & 7);
                uint32_t kch = (uint32_t)(ks * 2 + ((lane >> 3) & 1));
                uint32_t o = (uint32_t)(n * 128) + ((kch ^ (uint32_t)(n & 7)) << 4);
                ldsm4(Bh, sb + OFF_W3H + o);
                ldsm4(Bl, sb + OFF_W3L + o);
                #pragma unroll
                for (int mi = 0; mi < 2; ++mi)
                    #pragma unroll
                    for (int h = 0; h < 2; ++h) {
                        int ni = np * 2 + h;
                        mmah(acc3[mi][ni], Ah[mi], Bh[h*2], Bh[h*2+1]);
                        mmah(acc3[mi][ni], Ah[mi], Bl[h*2], Bl[h*2+1]);
                    }
            }
        }

        // ---------- epilogue 3: bias + masked softmax + stores ----------
        {
            #pragma unroll
            for (int mi = 0; mi < 2; ++mi)
                #pragma unroll
                for (int h = 0; h < 2; ++h) {
                    int r = wM * 32 + mi * 16 + (lane >> 2) + h * 8;
                    int scale = sSc[r];
                    float m = -3.4e38f;
                    #pragma unroll
                    for (int ni = 0; ni < 8; ++ni) {
                        int c0 = wN * 64 + ni * 8 + ((lane & 3) << 1);
                        float v0 = acc3[mi][ni][h*2]   + sB3[c0];
                        float v1 = acc3[mi][ni][h*2+1] + sB3[c0+1];
                        acc3[mi][ni][h*2]   = v0;
                        acc3[mi][ni][h*2+1] = v1;
                        if (c0     < scale) m = fmaxf(m, v0);
                        if (c0 + 1 < scale) m = fmaxf(m, v1);
                    }
                    m = fmaxf(m, __shfl_xor_sync(0xffffffffu, m, 1));
                    m = fmaxf(m, __shfl_xor_sync(0xffffffffu, m, 2));
                    if ((lane & 3) == 0) sPMax[wN * 128 + r] = m;
                }
            __syncthreads();
            #pragma unroll
            for (int mi = 0; mi < 2; ++mi)
                #pragma unroll
                for (int h = 0; h < 2; ++h) {
                    int r = wM * 32 + mi * 16 + (lane >> 2) + h * 8;
                    int scale = sSc[r];
                    float gm = fmaxf(fmaxf(sPMax[r], sPMax[128 + r]),
                                     fmaxf(sPMax[256 + r], sPMax[384 + r]));
                    float s = 0.f;
                    #pragma unroll
                    for (int ni = 0; ni < 8; ++ni) {
                        int c0 = wN * 64 + ni * 8 + ((lane & 3) << 1);
                        float e0 = (c0     < scale) ? __expf(acc3[mi][ni][h*2]   - gm) : 0.f;
                        float e1 = (c0 + 1 < scale) ? __expf(acc3[mi][ni][h*2+1] - gm) : 0.f;
                        acc3[mi][ni][h*2]   = e0;
                        acc3[mi][ni][h*2+1] = e1;
                        s += e0 + e1;
                    }
                    s += __shfl_xor_sync(0xffffffffu, s, 1);
                    s += __shfl_xor_sync(0xffffffffu, s, 2);
                    if ((lane & 3) == 0) sPSum[wN * 128 + r] = s;
                }
            __syncthreads();
            long long rowG0 = (long long)tile * TBR;
            #pragma unroll
            for (int mi = 0; mi < 2; ++mi)
                #pragma unroll
                for (int h = 0; h < 2; ++h) {
                    int r = wM * 32 + mi * 16 + (lane >> 2) + h * 8;
                    long long grow = rowG0 + r;
                    float inv = 1.f / (sPSum[r] + sPSum[128 + r] +
                                       sPSum[256 + r] + sPSum[384 + r]);
                    if (grow < (long long)Bsz) {
                        float* po = gProbs + (size_t)grow * OUTD;
                        #pragma unroll
                        for (int ni = 0; ni < 8; ++ni) {
                            int c0 = wN * 64 + ni * 8 + ((lane & 3) << 1);
                            float2 t;
                            t.x = acc3[mi][ni][h*2]   * inv;
                            t.y = acc3[mi][ni][h*2+1] * inv;
                            *(float2*)(po + c0) = t;
                        }
                    }
                }
            // mask output (coalesced)
            if (gMask) {
                #pragma unroll
                for (int i = 0; i < 16; ++i) {
                    int gg = tid + THREADS * i;
                    int row = gg >> 6, c4 = gg & 63;
                    long long grow = rowG0 + row;
                    if (grow < (long long)Bsz) {
                        int sc = sSc[row];
                        int c0 = c4 * 4;
                        float4 t;
                        t.x = (c0     < sc) ? 1.f : 0.f;
                        t.y = (c0 + 1 < sc) ? 1.f : 0.f;
                        t.z = (c0 + 2 < sc) ? 1.f : 0.f;
                        t.w = (c0 + 3 < sc) ? 1.f : 0.f;
                        *(float4*)(gMask + (size_t)grow * OUTD + c0) = t;
                    }
                }
            }
        }
        __syncthreads();   // protect buffers before next tile
    }
}

extern "C" void kernel_launch(void* const* d_in, const int* in_sizes, int n_in,
                              void* d_out, int out_size)
{
    const float* gIn    = (const float*)d_in[0];
    const int*   gScale = (const int*)  d_in[1];
    const float* gW1    = (const float*)d_in[2];
    const float* gB1    = (const float*)d_in[3];
    const float* gW2    = (const float*)d_in[4];
    const float* gB2    = (const float*)d_in[5];
    const float* gW3    = (const float*)d_in[6];
    const float* gB3    = (const float*)d_in[7];

    int Bsz = in_sizes[0] / IN_DIM;
    int numTiles = (Bsz + TBR - 1) / TBR;

    float* gProbs = (float*)d_out;
    float* gMask  = nullptr;
    long long need2 = 2LL * Bsz * OUTD;
    if ((long long)out_size >= need2)
        gMask = gProbs + (size_t)Bsz * OUTD;

    cudaFuncSetAttribute(policy_mma_kernel,
                         cudaFuncAttributeMaxDynamicSharedMemorySize, SMEM_BYTES);

    int smCount = 148;
    cudaDeviceGetAttribute(&smCount, cudaDevAttrMultiProcessorCount, 0);
    int grid = numTiles < smCount ? numTiles : smCount;

    policy_mma_kernel<<<grid, THREADS, SMEM_BYTES>>>(
        gIn, gScale, gW1, gB1, gW2, gB2, gW3, gB3,
        gProbs, gMask, Bsz, numTiles);
}